// round 10
// baseline (speedup 1.0000x reference)
#include <cuda_runtime.h>
#include <cuda_fp16.h>

// Problem constants
#define Kc    9
#define NCc   13
#define NAc   5
#define NBc   128
#define NHc   26
#define NWc   26
#define NTc   50
#define Lc    21          // 2K+3
#define NPIX  (NHc*NWc)   // 676
#define NANCH (NAc*NHc*NWc) // 3380
#define CH    (2*Kc+1+NCc) // 32
#define NBMW  106          // ceil(3380/32)

#define THf     80.0f
#define TH2f    6400.0f
// fp16 screen slack threshold: 82^2. fp16 round-off near the d=80 boundary
// is bounded by ~210 in d^2 units; margin 6724-6400=324 covers it, so the
// fp16 screen NEVER misses a corner that is truly inside d<80.
#define TH2SLK  6724.0f
#define SILf    0.6f
#define OBJf    5.0f
// 1/(exp(2)-1)
#define INVC0   0.15651764274966574f

#define SXc (640.0f/26.0f)
#define SYc (480.0f/26.0f)

typedef unsigned long long ull;
typedef unsigned int uint;

// Scratch (device globals — no allocation allowed)
// fp32 exact table (cold paths): per (b,t) 20 floats, group g in 0..3:
//   [g*4+0]=-gx_{2g} [g*4+1]=-gx_{2g+1} [g*4+2]=-gy_{2g} [g*4+3]=-gy_{2g+1}
//   [16..19] = corner 8 duplicated
__device__ __align__(16) float d_gtn[NBc*NTc*20];
// fp16 screen table (hot loop): per (b,t) 12 uints (half2 each):
//   [0]=ngx01 [1]=ngy01 [2]=ngx23 [3]=ngy23 [4]=ngx45 [5]=ngy45
//   [6]=ngx67 [7]=ngy67 [8]=ngx88(dup) [9]=ngy88(dup) [10,11]=pad
__device__ __align__(16) uint  d_gth[NBc*NTc*12];
__device__ float d_txv[NBc*NTc*Kc];
__device__ float d_tyv[NBc*NTc*Kc];
__device__ float d_conft[NBc*NTc];
__device__ float d_tclsA[NBc*NTc];
__device__ int   d_codeA[NBc*NTc];
__device__ int   d_nvalid[NBc];

__constant__ float c_anch[10] = {1.482f,2.2412f,2.0501f,3.1265f,2.3946f,
                                 4.6891f,3.1018f,3.991f,3.4879f,5.8851f};

__device__ __forceinline__ float sigmoidf_(float x) { return 1.0f/(1.0f+expf(-x)); }

__device__ __forceinline__ uint h2u(__half2 h) {
    return *reinterpret_cast<uint*>(&h);
}
__device__ __forceinline__ __half2 u2h(uint u) {
    return *reinterpret_cast<__half2*>(&u);
}
// d^2 - TH2SLK for a corner pair, fp16x2
__device__ __forceinline__ uint h2d2(uint phx, uint phy, uint ngx, uint ngy,
                                     __half2 nth2) {
    __half2 dx = __hadd2(u2h(phx), u2h(ngx));
    __half2 dy = __hadd2(u2h(phy), u2h(ngy));
    __half2 r  = __hfma2(dx, dx, __hfma2(dy, dy, nth2));
    return h2u(r);
}
// merge sign bits of 4 fp16 values (2 half2 regs) into bytes 0..3 (0xFF/0x00)
__device__ __forceinline__ uint prmt4(uint a, uint b) {
    uint r;
    asm("prmt.b32 %0, %1, %2, 0x0000FDB9;" : "=r"(r) : "r"(a), "r"(b));
    return r;
}
// sign bits of one half2 -> bytes 0,1
__device__ __forceinline__ uint prmt2s(uint a) {
    uint r;
    asm("prmt.b32 %0, %1, %1, 0x000000B9;" : "=r"(r) : "r"(a));
    return r;
}
__device__ __forceinline__ int dp4a_sel(uint s, uint sel, int acc) {
    int r;
    asm("dp4a.s32.s32 %0, %1, %2, %3;" : "=r"(r) : "r"(s), "r"(sel), "r"(acc));
    return r;
}

// One block per batch; thread t handles target t. Also zeroes the loss scalar.
__global__ void region_prep(const float* __restrict__ out,
                            const float* __restrict__ tgt,
                            float* __restrict__ loss)
{
    int b = blockIdx.x;
    int t = threadIdx.x;
    if (b == 0 && t == 0) loss[0] = 0.0f;

    __shared__ int sflag[NTc];
    if (t < NTc)
        sflag[t] = (tgt[(size_t)b*NTc*Lc + (size_t)t*Lc + 1] != 0.0f) ? 1 : 0;
    __syncthreads();
    if (t == 0) {
        int nv = NTc;
        for (int q = 0; q < NTc; ++q) if (!sflag[q]) { nv = q; break; }
        d_nvalid[b] = nv;
    }
    if (t >= NTc) return;

    const float* row = tgt + (size_t)b*NTc*Lc + (size_t)t*Lc;
    float gxr[Kc], gyr[Kc];
#pragma unroll
    for (int k = 0; k < Kc; ++k) { gxr[k] = row[1+2*k]; gyr[k] = row[2+2*k]; }

    int gi0 = (int)floorf(gxr[0]*(float)NWc);
    int gj0 = (int)floorf(gyr[0]*(float)NHc);
    gi0 = min(max(gi0, 0), NWc-1);
    gj0 = min(max(gj0, 0), NHc-1);

    int idx = b*NTc + t;

    float gpx[Kc], gpy[Kc];
#pragma unroll
    for (int k = 0; k < Kc; ++k) {
        gpx[k] = gxr[k]*640.0f;
        gpy[k] = gyr[k]*480.0f;
        d_txv[idx*Kc+k] = gxr[k]*(float)NWc - (float)gi0;
        d_tyv[idx*Kc+k] = gyr[k]*(float)NHc - (float)gj0;
    }
    float* gt = &d_gtn[idx*20];
#pragma unroll
    for (int g = 0; g < 4; ++g) {
        gt[g*4+0] = -gpx[2*g];  gt[g*4+1] = -gpx[2*g+1];
        gt[g*4+2] = -gpy[2*g];  gt[g*4+3] = -gpy[2*g+1];
    }
    gt[16] = -gpx[8]; gt[17] = -gpx[8]; gt[18] = -gpy[8]; gt[19] = -gpy[8];

    uint* gh = &d_gth[idx*12];
#pragma unroll
    for (int g = 0; g < 4; ++g) {
        gh[2*g+0] = h2u(__floats2half2_rn(-gpx[2*g], -gpx[2*g+1]));
        gh[2*g+1] = h2u(__floats2half2_rn(-gpy[2*g], -gpy[2*g+1]));
    }
    gh[8] = h2u(__floats2half2_rn(-gpx[8], -gpx[8]));
    gh[9] = h2u(__floats2half2_rn(-gpy[8], -gpy[8]));
    gh[10] = 0u; gh[11] = 0u;

    // best anchor by IoU on (gw, gh); first max wins (strict >)
    float gw = row[Lc-2]*(float)NWc;
    float ghh = row[Lc-1]*(float)NHc;
    float best = -1.0f; int bn = 0;
#pragma unroll
    for (int a = 0; a < NAc; ++a) {
        float aw = c_anch[2*a], ah = c_anch[2*a+1];
        float mw = fminf(aw, gw), mh = fminf(ah, ghh);
        float inter = mw*mh;
        float iou = inter / (aw*ah + gw*ghh - inter);
        if (iou > best) { best = iou; bn = a; }
    }
    d_codeA[idx] = bn*NPIX + gj0*NWc + gi0;
    d_tclsA[idx] = row[0];

    // conf_t: gather pred box from batch (b-1 mod NB), anchor NA-1, cell (gj0, gi0)
    int bp = (b + NBc - 1) % NBc;
    const float* cb = out + ((size_t)(bp*NAc + (NAc-1))*CH)*NPIX
                          + (size_t)(gj0*NWc + gi0);
    float acc = 0.0f;
#pragma unroll
    for (int k = 0; k < Kc; ++k) {
        float xv = cb[(2*k)*NPIX];
        float yv = cb[(2*k+1)*NPIX];
        if (k == 0) { xv = sigmoidf_(xv); yv = sigmoidf_(yv); }
        float px = (xv + (float)gi0) * (1.0f/(float)NWc);
        float py = (yv + (float)gj0) * (1.0f/(float)NHc);
        float dx = (px - gxr[k]) * 640.0f;
        float dy = (py - gyr[k]) * 480.0f;
        float d2 = fmaf(dx, dx, dy*dy);
        if (d2 < TH2f) {
            float d = sqrtf(d2);
            acc += (expf(2.0f - d*0.025f) - 1.0f) * INVC0;
        }
    }
    d_conft[idx] = acc * (1.0f/(float)Kc);
}

// COLD: full exact (fp32) rescan of all targets for one cell, reading the
// exact fp32 table from GLOBAL. Decision logic identical to reference:
// count corners with exact d^2 < TH^2; if >= 6, exact corner-conf sum; max.
__device__ __noinline__ float rescan_cell(const float* __restrict__ cb,
                                          const float* __restrict__ gtb,
                                          int cell, int nv)
{
    int a = cell / NPIX, pos = cell - a*NPIX;
    int jj = pos / NWc, ii = pos - jj*NWc;
    float fx = (float)ii * SXc, fy = (float)jj * SYc;
    float pxs[Kc], pys[Kc];
#pragma unroll
    for (int k = 0; k < Kc; ++k) {
        float xv = cb[(2*k)*NPIX];
        float yv = cb[(2*k+1)*NPIX];
        if (k == 0) { xv = sigmoidf_(xv); yv = sigmoidf_(yv); }
        pxs[k] = fmaf(xv, SXc, fx);
        pys[k] = fmaf(yv, SYc, fy);
    }
    float m = 0.0f;
    for (int t = 0; t < nv; ++t) {
        const float* tp = gtb + t*20;
        int cnt = 0;
        float d2s[Kc];
#pragma unroll
        for (int k = 0; k < Kc; ++k) {
            float ngx = tp[(k>>1)*4 + (k&1)];
            float ngy = tp[(k>>1)*4 + 2 + (k&1)];
            float dx = pxs[k] + ngx;
            float dy = pys[k] + ngy;
            float dd = fmaf(dx, dx, fmaf(dy, dy, -TH2f));
            d2s[k] = dd;
            cnt += (__float_as_uint(dd) >> 31);
        }
        if (cnt >= 6) {
            float acc = 0.0f;
#pragma unroll
            for (int k = 0; k < Kc; ++k) {
                if (d2s[k] < 0.0f) {
                    float d = sqrtf(d2s[k] + TH2f);
                    acc += (expf(2.0f - d*0.025f) - 1.0f) * INVC0;
                }
            }
            m = fmaxf(m, acc);
        }
    }
    return m;
}

// rare per-object-cell / noobj epilogue
__device__ __noinline__ float cell_loss(const float* __restrict__ cb,
                                        int b, int win, int doconf, int over_sil,
                                        const float* __restrict__ sconft,
                                        const float* __restrict__ stcls)
{
    float contrib = 0.0f;
    if (win >= 0) {
        const float* txp = &d_txv[(b*NTc + win)*Kc];
        const float* typ = &d_tyv[(b*NTc + win)*Kc];
        float cl = 0.0f;
#pragma unroll
        for (int k = 0; k < Kc; ++k) {
            float xv = cb[(2*k)*NPIX];
            float yv = cb[(2*k+1)*NPIX];
            if (k == 0) { xv = sigmoidf_(xv); yv = sigmoidf_(yv); }
            float exd = xv - txp[k];
            float eyd = yv - typ[k];
            cl += exd*exd + eyd*eyd;
        }
        contrib = 0.5f*cl;

        float lg[NCc];
        float mx = -1e30f;
#pragma unroll
        for (int c = 0; c < NCc; ++c) {
            lg[c] = cb[(2*Kc+1+c)*NPIX];
            mx = fmaxf(mx, lg[c]);
        }
        float se = 0.0f;
#pragma unroll
        for (int c = 0; c < NCc; ++c) se += expf(lg[c]-mx);
        int lab = (int)stcls[win];
        lab = min(max(lab, 0), NCc-1);
        contrib += (mx + logf(se)) - lg[lab];

        if (doconf) {
            float conf = sigmoidf_(cb[(2*Kc)*NPIX]);
            float dc = conf - sconft[win];
            contrib += 0.5f*OBJf*dc*dc;
        }
    } else {
        if (doconf && !over_sil) {
            float conf = sigmoidf_(cb[(2*Kc)*NPIX]);
            contrib += 0.5f*conf*conf;
        }
    }
    return contrib;
}

// fill packed fp16 corner pairs (groups 0..3) + fp32 corner 8 for one cell
__device__ __forceinline__ void cell_setup(const float* __restrict__ cb,
                                           int cell, uint* phx, uint* phy,
                                           float& px8, float& py8)
{
    int a = cell / NPIX, pos = cell - a*NPIX;
    int jj = pos / NWc, ii = pos - jj*NWc;
    float fx = (float)ii * SXc, fy = (float)jj * SYc;
#pragma unroll
    for (int g = 0; g < 4; ++g) {
        float xv0 = cb[(4*g+0)*NPIX];
        float yv0 = cb[(4*g+1)*NPIX];
        float xv1 = cb[(4*g+2)*NPIX];
        float yv1 = cb[(4*g+3)*NPIX];
        if (g == 0) { xv0 = sigmoidf_(xv0); yv0 = sigmoidf_(yv0); }
        float p0 = fmaf(xv0, SXc, fx), q0 = fmaf(yv0, SYc, fy);
        float p1 = fmaf(xv1, SXc, fx), q1 = fmaf(yv1, SYc, fy);
        phx[g] = h2u(__floats2half2_rn(p0, p1));
        phy[g] = h2u(__floats2half2_rn(q0, q1));
    }
    px8 = fmaf(cb[16*NPIX], SXc, fx);
    py8 = fmaf(cb[17*NPIX], SYc, fy);
}

// grid: (ceil(NANCH/512), NB) ; each thread handles 2 cells (tid, tid+256)
__global__ __launch_bounds__(256, 5)
void region_main(const float* __restrict__ out,
                 const int*   __restrict__ ep,
                 float* __restrict__ loss)
{
    int b   = blockIdx.y;
    int tid = threadIdx.x;
    int cellA = blockIdx.x*512 + tid;
    int cellB = cellA + 256;

    __shared__ __align__(16) uint sgh[NTc*12];
    __shared__ float sconft[NTc], stcls[NTc];
    __shared__ int   scode[NTc];
    __shared__ uint  sbm[NBMW];
    __shared__ float wred[8];
    __shared__ int   snv;

    {
        const uint4* src = (const uint4*)&d_gth[b*NTc*12];
        uint4* dst = (uint4*)sgh;
        for (int i2 = tid; i2 < NTc*12/4; i2 += 256) dst[i2] = src[i2];
    }
    if (tid < NBMW) sbm[tid] = 0u;
    if (tid == 0) snv = d_nvalid[b];
    if (tid < NTc) {
        sconft[tid] = d_conft[b*NTc + tid];
        stcls[tid]  = d_tclsA[b*NTc + tid];
        scode[tid]  = d_codeA[b*NTc + tid];
    }
    __syncthreads();      // bitmap fully zeroed + scode/snv visible
    if (tid < NTc && tid < snv) {
        int code = scode[tid];
        atomicOr(&sbm[code >> 5], 1u << (code & 31));
    }
    __syncthreads();

    int actA = (cellA < NANCH), actB = (cellB < NANCH);

    // per-cell packed fp16 state: groups 0..3 per cell + merged corner-8 pair
    uint phxA[4], phyA[4], phxB[4], phyB[4], px8p, py8p;
    const float* cbA = out;
    const float* cbB = out;

    {
        uint big = h2u(__floats2half2_rn(60000.0f, 60000.0f));
#pragma unroll
        for (int g = 0; g < 4; ++g) { phxA[g]=big; phyA[g]=big; phxB[g]=big; phyB[g]=big; }
    }
    float px8A = 60000.0f, py8A = 60000.0f, px8B = 60000.0f, py8B = 60000.0f;
    if (actA) {
        cbA = out + ((size_t)(b*NAc + cellA/NPIX)*CH)*NPIX + (size_t)(cellA%NPIX);
        cell_setup(cbA, cellA, phxA, phyA, px8A, py8A);
    }
    if (actB) {
        cbB = out + ((size_t)(b*NAc + cellB/NPIX)*CH)*NPIX + (size_t)(cellB%NPIX);
        cell_setup(cbB, cellB, phxB, phyB, px8B, py8B);
    }
    px8p = h2u(__floats2half2_rn(px8A, px8B));
    py8p = h2u(__floats2half2_rn(py8A, py8B));

    const __half2 nth2 = __floats2half2_rn(-TH2SLK, -TH2SLK);
    int nv = snv;
    int maccA = 0, maccB = 0;

    // BRANCHLESS fp16 hot loop: track min(-count) per cell.
#pragma unroll 1
    for (int t = 0; t < nv; ++t) {
        const uint4* q = (const uint4*)&sgh[t*12];
        uint4 Q0 = q[0];   // ngx01, ngy01, ngx23, ngy23
        uint4 Q1 = q[1];   // ngx45, ngy45, ngx67, ngy67
        uint4 Q2 = q[2];   // ngx88, ngy88, pad, pad

        uint dA0 = h2d2(phxA[0], phyA[0], Q0.x, Q0.y, nth2);
        uint dA1 = h2d2(phxA[1], phyA[1], Q0.z, Q0.w, nth2);
        uint dA2 = h2d2(phxA[2], phyA[2], Q1.x, Q1.y, nth2);
        uint dA3 = h2d2(phxA[3], phyA[3], Q1.z, Q1.w, nth2);
        uint dB0 = h2d2(phxB[0], phyB[0], Q0.x, Q0.y, nth2);
        uint dB1 = h2d2(phxB[1], phyB[1], Q0.z, Q0.w, nth2);
        uint dB2 = h2d2(phxB[2], phyB[2], Q1.x, Q1.y, nth2);
        uint dB3 = h2d2(phxB[3], phyB[3], Q1.z, Q1.w, nth2);
        uint d8  = h2d2(px8p,    py8p,    Q2.x, Q2.y, nth2); // (A8, B8)

        uint s8 = prmt2s(d8);
        int accA = dp4a_sel(prmt4(dA0, dA1), 0x01010101u,
                   dp4a_sel(prmt4(dA2, dA3), 0x01010101u,
                   dp4a_sel(s8, 0x00000001u, 0)));
        int accB = dp4a_sel(prmt4(dB0, dB1), 0x01010101u,
                   dp4a_sel(prmt4(dB2, dB3), 0x01010101u,
                   dp4a_sel(s8, 0x00000100u, 0)));

        maccA = min(maccA, accA);
        maccB = min(maccB, accB);
    }

    // acc = -(#corners inside slack radius). Reference needs >= 6 corners
    // within TH for mean-conf > 0.6; fp16 screen is a guaranteed superset.
    const float* gtb = &d_gtn[b*NTc*20];
    float mA = 0.0f, mB = 0.0f;
    if (maccA <= -6) mA = rescan_cell(cbA, gtb, cellA, nv);
    if (maccB <= -6) mB = rescan_cell(cbB, gtb, cellB, nv);

    int doconf = (ep[0] > 15) ? 1 : 0;
    float contrib = 0.0f;
    if (actA) {
        int over = (mA * (1.0f/(float)Kc)) > SILf;
        int win = -1;
        if (sbm[cellA >> 5] & (1u << (cellA & 31))) {
            for (int t = nv-1; t >= 0; --t)
                if (scode[t] == cellA) { win = t; break; }
        }
        if (win >= 0 || (doconf && !over))
            contrib += cell_loss(cbA, b, win, doconf, over, sconft, stcls);
    }
    if (actB) {
        int over = (mB * (1.0f/(float)Kc)) > SILf;
        int win = -1;
        if (sbm[cellB >> 5] & (1u << (cellB & 31))) {
            for (int t = nv-1; t >= 0; --t)
                if (scode[t] == cellB) { win = t; break; }
        }
        if (win >= 0 || (doconf && !over))
            contrib += cell_loss(cbB, b, win, doconf, over, sconft, stcls);
    }

    // warp-shuffle reduction + one atomic per block
#pragma unroll
    for (int off = 16; off > 0; off >>= 1)
        contrib += __shfl_down_sync(0xFFFFFFFFu, contrib, off);
    int lane = tid & 31, wid = tid >> 5;
    if (lane == 0) wred[wid] = contrib;
    __syncthreads();
    if (tid < 8) {
        float v = wred[tid];
#pragma unroll
        for (int off = 4; off > 0; off >>= 1)
            v += __shfl_down_sync(0xFFu, v, off);
        if (tid == 0) atomicAdd(loss, v);
    }
}

extern "C" void kernel_launch(void* const* d_in, const int* in_sizes, int n_in,
                              void* d_out, int out_size)
{
    const float* out = (const float*)d_in[0];
    const float* tgt = (const float*)d_in[1];
    const int*   ep  = (const int*)d_in[2];
    float* loss = (float*)d_out;

    region_prep<<<NBc, 64>>>(out, tgt, loss);
    dim3 g((NANCH + 511)/512, NBc);
    region_main<<<g, 256>>>(out, ep, loss);
}

// round 11
// speedup vs baseline: 1.1781x; 1.1781x over previous
#include <cuda_runtime.h>

// Problem constants
#define Kc    9
#define NCc   13
#define NAc   5
#define NBc   128
#define NHc   26
#define NWc   26
#define NTc   50
#define Lc    21          // 2K+3
#define NPIX  (NHc*NWc)   // 676
#define NANCH (NAc*NHc*NWc) // 3380
#define CH    (2*Kc+1+NCc) // 32
#define NBMW  106          // ceil(3380/32)

#define THf     80.0f
#define TH2f    6400.0f
#define SILf    0.6f
#define OBJf    5.0f
// 1/(exp(2)-1)
#define INVC0   0.15651764274966574f

#define SXc (640.0f/26.0f)
#define SYc (480.0f/26.0f)

typedef unsigned long long ull;
typedef unsigned int uint;

// Scratch (device globals — no allocation allowed)
// Per (b,t): 20 floats = 5 float4; group g in 0..3 (corner pair 2g,2g+1):
//   [g*4+0]=-gx_{2g}  [g*4+1]=-gx_{2g+1}  [g*4+2]=-gy_{2g}  [g*4+3]=-gy_{2g+1}
// [16]=-gx8 [17]=-gy8 [18]=pad [19]=pad
__device__ __align__(16) float d_gtn[NBc*NTc*20];
__device__ float d_txv[NBc*NTc*Kc];
__device__ float d_tyv[NBc*NTc*Kc];
__device__ float d_conft[NBc*NTc];
__device__ float d_tclsA[NBc*NTc];
__device__ int   d_codeA[NBc*NTc];
__device__ int   d_nvalid[NBc];

__constant__ float c_anch[10] = {1.482f,2.2412f,2.0501f,3.1265f,2.3946f,
                                 4.6891f,3.1018f,3.991f,3.4879f,5.8851f};

__device__ __forceinline__ float sigmoidf_(float x) { return 1.0f/(1.0f+expf(-x)); }

__device__ __forceinline__ ull pack2(float lo, float hi) {
    ull r;
    asm("mov.b64 %0, {%1, %2};" : "=l"(r) : "f"(lo), "f"(hi));
    return r;
}
__device__ __forceinline__ ull fma2_(ull a, ull b, ull c) {
    ull d;
    asm("fma.rn.f32x2 %0, %1, %2, %3;" : "=l"(d) : "l"(a), "l"(b), "l"(c));
    return d;
}
__device__ __forceinline__ ull add2_(ull a, ull b) {
    ull d;
    asm("add.rn.f32x2 %0, %1, %2;" : "=l"(d) : "l"(a), "l"(b));
    return d;
}
// d^2 - TH^2 for a corner pair (direct form)
__device__ __forceinline__ ull dist2m(ull px, ull py, ull ngx, ull ngy, ull nTH2) {
    ull dx = add2_(px, ngx);
    ull dy = add2_(py, ngy);
    return fma2_(dx, dx, fma2_(dy, dy, nTH2));
}
// sign bytes of the two packed floats in d -> bytes 0,1 as 0xFF/0x00
__device__ __forceinline__ uint prmt_sgn(ull d) {
    uint lo = (uint)d, hi = (uint)(d >> 32), r;
    asm("prmt.b32 %0, %1, %2, 0x000000FB;" : "=r"(r) : "r"(lo), "r"(hi));
    return r;
}
// acc += dot(sign bytes, sel)  (-1 per inside corner)
__device__ __forceinline__ int dp4a_sel(uint s, uint sel, int acc) {
    int r;
    asm("dp4a.s32.s32 %0, %1, %2, %3;" : "=r"(r) : "r"(s), "r"(sel), "r"(acc));
    return r;
}

// One block per batch; thread t handles target t. Also zeroes the loss scalar.
__global__ void region_prep(const float* __restrict__ out,
                            const float* __restrict__ tgt,
                            float* __restrict__ loss)
{
    int b = blockIdx.x;
    int t = threadIdx.x;
    if (b == 0 && t == 0) loss[0] = 0.0f;

    __shared__ int sflag[NTc];
    if (t < NTc)
        sflag[t] = (tgt[(size_t)b*NTc*Lc + (size_t)t*Lc + 1] != 0.0f) ? 1 : 0;
    __syncthreads();
    if (t == 0) {
        int nv = NTc;
        for (int q = 0; q < NTc; ++q) if (!sflag[q]) { nv = q; break; }
        d_nvalid[b] = nv;
    }
    if (t >= NTc) return;

    const float* row = tgt + (size_t)b*NTc*Lc + (size_t)t*Lc;
    float gxr[Kc], gyr[Kc];
#pragma unroll
    for (int k = 0; k < Kc; ++k) { gxr[k] = row[1+2*k]; gyr[k] = row[2+2*k]; }

    int gi0 = (int)floorf(gxr[0]*(float)NWc);
    int gj0 = (int)floorf(gyr[0]*(float)NHc);
    gi0 = min(max(gi0, 0), NWc-1);
    gj0 = min(max(gj0, 0), NHc-1);

    int idx = b*NTc + t;

    float gpx[Kc], gpy[Kc];
#pragma unroll
    for (int k = 0; k < Kc; ++k) {
        gpx[k] = gxr[k]*640.0f;
        gpy[k] = gyr[k]*480.0f;
        d_txv[idx*Kc+k] = gxr[k]*(float)NWc - (float)gi0;
        d_tyv[idx*Kc+k] = gyr[k]*(float)NHc - (float)gj0;
    }
    float* gt = &d_gtn[idx*20];
#pragma unroll
    for (int g = 0; g < 4; ++g) {
        gt[g*4+0] = -gpx[2*g];  gt[g*4+1] = -gpx[2*g+1];
        gt[g*4+2] = -gpy[2*g];  gt[g*4+3] = -gpy[2*g+1];
    }
    gt[16] = -gpx[8]; gt[17] = -gpy[8]; gt[18] = 0.0f; gt[19] = 0.0f;

    // best anchor by IoU on (gw, gh); first max wins (strict >)
    float gw = row[Lc-2]*(float)NWc;
    float gh = row[Lc-1]*(float)NHc;
    float best = -1.0f; int bn = 0;
#pragma unroll
    for (int a = 0; a < NAc; ++a) {
        float aw = c_anch[2*a], ah = c_anch[2*a+1];
        float mw = fminf(aw, gw), mh = fminf(ah, gh);
        float inter = mw*mh;
        float iou = inter / (aw*ah + gw*gh - inter);
        if (iou > best) { best = iou; bn = a; }
    }
    d_codeA[idx] = bn*NPIX + gj0*NWc + gi0;
    d_tclsA[idx] = row[0];

    // conf_t: gather pred box from batch (b-1 mod NB), anchor NA-1, cell (gj0, gi0)
    int bp = (b + NBc - 1) % NBc;
    const float* cb = out + ((size_t)(bp*NAc + (NAc-1))*CH)*NPIX
                          + (size_t)(gj0*NWc + gi0);
    float acc = 0.0f;
#pragma unroll
    for (int k = 0; k < Kc; ++k) {
        float xv = cb[(2*k)*NPIX];
        float yv = cb[(2*k+1)*NPIX];
        if (k == 0) { xv = sigmoidf_(xv); yv = sigmoidf_(yv); }
        float px = (xv + (float)gi0) * (1.0f/(float)NWc);
        float py = (yv + (float)gj0) * (1.0f/(float)NHc);
        float dx = (px - gxr[k]) * 640.0f;
        float dy = (py - gyr[k]) * 480.0f;
        float d2 = fmaf(dx, dx, dy*dy);
        if (d2 < TH2f) {
            float d = sqrtf(d2);
            acc += (expf(2.0f - d*0.025f) - 1.0f) * INVC0;
        }
    }
    d_conft[idx] = acc * (1.0f/(float)Kc);
}

// COLD: full exact rescan of all targets for one cell. Decision logic
// identical to the screen/reference: count corners with d^2 < TH^2; if >= 6,
// exact corner-conf sum; max over targets.
__device__ __noinline__ float rescan_cell(const float* __restrict__ cb,
                                          const float* __restrict__ sgt,
                                          int cell, int nv)
{
    int a = cell / NPIX, pos = cell - a*NPIX;
    int jj = pos / NWc, ii = pos - jj*NWc;
    float fx = (float)ii * SXc, fy = (float)jj * SYc;
    float pxs[Kc], pys[Kc];
#pragma unroll
    for (int k = 0; k < Kc; ++k) {
        float xv = cb[(2*k)*NPIX];
        float yv = cb[(2*k+1)*NPIX];
        if (k == 0) { xv = sigmoidf_(xv); yv = sigmoidf_(yv); }
        pxs[k] = fmaf(xv, SXc, fx);
        pys[k] = fmaf(yv, SYc, fy);
    }
    float m = 0.0f;
    for (int t = 0; t < nv; ++t) {
        const float* tp = &sgt[t*20];
        int cnt = 0;
        float d2s[Kc];
#pragma unroll
        for (int k = 0; k < Kc; ++k) {
            float ngx = (k < 8) ? tp[(k>>1)*4 + (k&1)]     : tp[16];
            float ngy = (k < 8) ? tp[(k>>1)*4 + 2 + (k&1)] : tp[17];
            float dx = pxs[k] + ngx;
            float dy = pys[k] + ngy;
            float dd = fmaf(dx, dx, fmaf(dy, dy, -TH2f));
            d2s[k] = dd;
            cnt += (__float_as_uint(dd) >> 31);
        }
        if (cnt >= 6) {
            float acc = 0.0f;
#pragma unroll
            for (int k = 0; k < Kc; ++k) {
                if (d2s[k] < 0.0f) {
                    float d = sqrtf(d2s[k] + TH2f);
                    acc += (expf(2.0f - d*0.025f) - 1.0f) * INVC0;
                }
            }
            m = fmaxf(m, acc);
        }
    }
    return m;
}

// rare per-object-cell / noobj epilogue
__device__ __noinline__ float cell_loss(const float* __restrict__ cb,
                                        int b, int win, int doconf, int over_sil,
                                        const float* __restrict__ sconft,
                                        const float* __restrict__ stcls)
{
    float contrib = 0.0f;
    if (win >= 0) {
        const float* txp = &d_txv[(b*NTc + win)*Kc];
        const float* typ = &d_tyv[(b*NTc + win)*Kc];
        float cl = 0.0f;
#pragma unroll
        for (int k = 0; k < Kc; ++k) {
            float xv = cb[(2*k)*NPIX];
            float yv = cb[(2*k+1)*NPIX];
            if (k == 0) { xv = sigmoidf_(xv); yv = sigmoidf_(yv); }
            float exd = xv - txp[k];
            float eyd = yv - typ[k];
            cl += exd*exd + eyd*eyd;
        }
        contrib = 0.5f*cl;

        float lg[NCc];
        float mx = -1e30f;
#pragma unroll
        for (int c = 0; c < NCc; ++c) {
            lg[c] = cb[(2*Kc+1+c)*NPIX];
            mx = fmaxf(mx, lg[c]);
        }
        float se = 0.0f;
#pragma unroll
        for (int c = 0; c < NCc; ++c) se += expf(lg[c]-mx);
        int lab = (int)stcls[win];
        lab = min(max(lab, 0), NCc-1);
        contrib += (mx + logf(se)) - lg[lab];

        if (doconf) {
            float conf = sigmoidf_(cb[(2*Kc)*NPIX]);
            float dc = conf - sconft[win];
            contrib += 0.5f*OBJf*dc*dc;
        }
    } else {
        if (doconf && !over_sil) {
            float conf = sigmoidf_(cb[(2*Kc)*NPIX]);
            contrib += 0.5f*conf*conf;
        }
    }
    return contrib;
}

// grid: (14, NB) ; one thread per cell (256 cells per block)
__global__ __launch_bounds__(256, 4)
void region_main(const float* __restrict__ out,
                 const int*   __restrict__ ep,
                 float* __restrict__ loss)
{
    int b   = blockIdx.y;
    int tid = threadIdx.x;
    int cell = blockIdx.x*256 + tid;

    __shared__ __align__(16) float sgt[NTc*20];
    __shared__ float sconft[NTc], stcls[NTc];
    __shared__ int   scode[NTc];
    __shared__ uint  sbm[NBMW];
    __shared__ float wred[8];
    __shared__ int   snv;

    {
        const float4* src = (const float4*)&d_gtn[b*NTc*20];
        float4* dst = (float4*)sgt;
        for (int i2 = tid; i2 < NTc*20/4; i2 += 256) dst[i2] = src[i2];
    }
    if (tid < NBMW) sbm[tid] = 0u;
    if (tid == 0) snv = d_nvalid[b];
    if (tid < NTc) {
        sconft[tid] = d_conft[b*NTc + tid];
        stcls[tid]  = d_tclsA[b*NTc + tid];
        scode[tid]  = d_codeA[b*NTc + tid];
    }
    __syncthreads();      // bitmap fully zeroed + scode/snv visible
    if (tid < NTc && tid < snv) {
        int code = scode[tid];
        atomicOr(&sbm[code >> 5], 1u << (code & 31));
    }
    __syncthreads();

    int act = (cell < NANCH);

    // per-cell packed state: 4 pair groups + scalar corner 8
    ull px[4], py[4];
    float px8 = 60000.0f, py8 = 60000.0f;
    const float* cb = out;
    {
        ull big = pack2(1e30f, 1e30f);
#pragma unroll
        for (int g = 0; g < 4; ++g) { px[g] = big; py[g] = big; }
    }
    if (act) {
        int a = cell / NPIX, pos = cell - a*NPIX;
        int jj = pos / NWc, ii = pos - jj*NWc;
        cb = out + ((size_t)(b*NAc + a)*CH)*NPIX + (size_t)pos;
        float fx = (float)ii * SXc, fy = (float)jj * SYc;
        float pxs[Kc], pys[Kc];
#pragma unroll
        for (int k = 0; k < Kc; ++k) {
            float xv = cb[(2*k)*NPIX];
            float yv = cb[(2*k+1)*NPIX];
            if (k == 0) { xv = sigmoidf_(xv); yv = sigmoidf_(yv); }
            pxs[k] = fmaf(xv, SXc, fx);
            pys[k] = fmaf(yv, SYc, fy);
        }
#pragma unroll
        for (int g = 0; g < 4; ++g) {
            px[g] = pack2(pxs[2*g], pxs[2*g+1]);
            py[g] = pack2(pys[2*g], pys[2*g+1]);
        }
        px8 = pxs[8]; py8 = pys[8];
    }

    const ull nTH2 = pack2(-TH2f, -TH2f);
    int nv = snv;
    int macc = 0;

    // BRANCHLESS hot loop, 1 cell; unroll 2 so next iteration's LDS overlap
    // the current iteration's dependent tail.
#pragma unroll 2
    for (int t = 0; t < nv; ++t) {
        const float* tp = &sgt[t*20];
        const ulonglong2* q = (const ulonglong2*)tp;
        ulonglong2 q0 = q[0], q1 = q[1], q2 = q[2], q3 = q[3];
        ull q4 = *(const ull*)(tp + 16);      // (-gx8, -gy8)

        ull d0 = dist2m(px[0], py[0], q0.x, q0.y, nTH2);
        ull d1 = dist2m(px[1], py[1], q1.x, q1.y, nTH2);
        ull d2 = dist2m(px[2], py[2], q2.x, q2.y, nTH2);
        ull d3 = dist2m(px[3], py[3], q3.x, q3.y, nTH2);

        float ngx8 = __uint_as_float((uint)q4);
        float ngy8 = __uint_as_float((uint)(q4 >> 32));
        float dx8 = px8 + ngx8;
        float dy8 = py8 + ngy8;
        float d8  = fmaf(dx8, dx8, fmaf(dy8, dy8, -TH2f));

        int acc = dp4a_sel(prmt_sgn(d0), 0x0101u,
                  dp4a_sel(prmt_sgn(d1), 0x0101u,
                  dp4a_sel(prmt_sgn(d2), 0x0101u,
                  dp4a_sel(prmt_sgn(d3), 0x0101u, 0))));
        acc -= (int)(__float_as_uint(d8) >> 31);

        macc = min(macc, acc);
    }

    // acc = -(#corners inside). mean-conf > 0.6 (sum > 5.4) requires >= 6
    // corners within TH (each corner conf <= 1). Cold rescan only if any
    // target could pass (per-lane rare).
    float m = 0.0f;
    if (macc <= -6) m = rescan_cell(cb, sgt, cell, nv);

    int doconf = (ep[0] > 15) ? 1 : 0;
    float contrib = 0.0f;
    if (act) {
        int over = (m * (1.0f/(float)Kc)) > SILf;
        int win = -1;
        if (sbm[cell >> 5] & (1u << (cell & 31))) {
            for (int t = nv-1; t >= 0; --t)
                if (scode[t] == cell) { win = t; break; }
        }
        if (win >= 0 || (doconf && !over))
            contrib = cell_loss(cb, b, win, doconf, over, sconft, stcls);
    }

    // warp-shuffle reduction + one atomic per block
#pragma unroll
    for (int off = 16; off > 0; off >>= 1)
        contrib += __shfl_down_sync(0xFFFFFFFFu, contrib, off);
    int lane = tid & 31, wid = tid >> 5;
    if (lane == 0) wred[wid] = contrib;
    __syncthreads();
    if (tid < 8) {
        float v = wred[tid];
#pragma unroll
        for (int off = 4; off > 0; off >>= 1)
            v += __shfl_down_sync(0xFFu, v, off);
        if (tid == 0) atomicAdd(loss, v);
    }
}

extern "C" void kernel_launch(void* const* d_in, const int* in_sizes, int n_in,
                              void* d_out, int out_size)
{
    const float* out = (const float*)d_in[0];
    const float* tgt = (const float*)d_in[1];
    const int*   ep  = (const int*)d_in[2];
    float* loss = (float*)d_out;

    region_prep<<<NBc, 64>>>(out, tgt, loss);
    dim3 g((NANCH + 255)/256, NBc);
    region_main<<<g, 256>>>(out, ep, loss);
}

// round 12
// speedup vs baseline: 1.3543x; 1.1496x over previous
#include <cuda_runtime.h>

// Problem constants
#define Kc    9
#define NCc   13
#define NAc   5
#define NBc   128
#define NHc   26
#define NWc   26
#define NTc   50
#define Lc    21          // 2K+3
#define NPIX  (NHc*NWc)   // 676
#define NANCH (NAc*NHc*NWc) // 3380
#define CH    (2*Kc+1+NCc) // 32
#define NBMW  106          // ceil(3380/32)

#define THf     80.0f
#define TH2f    6400.0f
#define SILf    0.6f
#define OBJf    5.0f
// 1/(exp(2)-1)
#define INVC0   0.15651764274966574f

#define SXc (640.0f/26.0f)
#define SYc (480.0f/26.0f)

typedef unsigned long long ull;
typedef unsigned int uint;

// Scratch (device globals — no allocation allowed)
// Per (b,t): 20 floats = 5 float4; group g in 0..3 (corner pair 2g,2g+1):
//   [g*4+0]=-gx_{2g}  [g*4+1]=-gx_{2g+1}  [g*4+2]=-gy_{2g}  [g*4+3]=-gy_{2g+1}
// [16]=-gx8 [17]=-gy8 [18]=pad [19]=pad
__device__ __align__(16) float d_gtn[NBc*NTc*20];
__device__ float d_txv[NBc*NTc*Kc];
__device__ float d_tyv[NBc*NTc*Kc];
__device__ float d_conft[NBc*NTc];
__device__ float d_tclsA[NBc*NTc];
__device__ int   d_codeA[NBc*NTc];
__device__ int   d_nvalid[NBc];

__constant__ float c_anch[10] = {1.482f,2.2412f,2.0501f,3.1265f,2.3946f,
                                 4.6891f,3.1018f,3.991f,3.4879f,5.8851f};

__device__ __forceinline__ float sigmoidf_(float x) { return 1.0f/(1.0f+expf(-x)); }

__device__ __forceinline__ ull pack2(float lo, float hi) {
    ull r;
    asm("mov.b64 %0, {%1, %2};" : "=l"(r) : "f"(lo), "f"(hi));
    return r;
}
__device__ __forceinline__ ull fma2_(ull a, ull b, ull c) {
    ull d;
    asm("fma.rn.f32x2 %0, %1, %2, %3;" : "=l"(d) : "l"(a), "l"(b), "l"(c));
    return d;
}
__device__ __forceinline__ ull add2_(ull a, ull b) {
    ull d;
    asm("add.rn.f32x2 %0, %1, %2;" : "=l"(d) : "l"(a), "l"(b));
    return d;
}
// d^2 - TH^2 for a corner pair (direct form)
__device__ __forceinline__ ull dist2m(ull px, ull py, ull ngx, ull ngy, ull nTH2) {
    ull dx = add2_(px, ngx);
    ull dy = add2_(py, ngy);
    return fma2_(dx, dx, fma2_(dy, dy, nTH2));
}
// sign bytes of the two packed floats in d -> bytes 0,1 as 0xFF/0x00
__device__ __forceinline__ uint prmt_sgn(ull d) {
    uint lo = (uint)d, hi = (uint)(d >> 32), r;
    asm("prmt.b32 %0, %1, %2, 0x000000FB;" : "=r"(r) : "r"(lo), "r"(hi));
    return r;
}
// acc += dot(sign bytes, sel)  (-1 per inside corner)
__device__ __forceinline__ int dp4a_sel(uint s, uint sel, int acc) {
    int r;
    asm("dp4a.s32.s32 %0, %1, %2, %3;" : "=r"(r) : "r"(s), "r"(sel), "r"(acc));
    return r;
}

// One block per batch; thread t handles target t. Also zeroes the loss scalar.
__global__ void region_prep(const float* __restrict__ out,
                            const float* __restrict__ tgt,
                            float* __restrict__ loss)
{
    int b = blockIdx.x;
    int t = threadIdx.x;
    if (b == 0 && t == 0) loss[0] = 0.0f;

    __shared__ int sflag[NTc];
    if (t < NTc)
        sflag[t] = (tgt[(size_t)b*NTc*Lc + (size_t)t*Lc + 1] != 0.0f) ? 1 : 0;
    __syncthreads();
    if (t == 0) {
        int nv = NTc;
        for (int q = 0; q < NTc; ++q) if (!sflag[q]) { nv = q; break; }
        d_nvalid[b] = nv;
    }
    if (t >= NTc) return;

    const float* row = tgt + (size_t)b*NTc*Lc + (size_t)t*Lc;
    float gxr[Kc], gyr[Kc];
#pragma unroll
    for (int k = 0; k < Kc; ++k) { gxr[k] = row[1+2*k]; gyr[k] = row[2+2*k]; }

    int gi0 = (int)floorf(gxr[0]*(float)NWc);
    int gj0 = (int)floorf(gyr[0]*(float)NHc);
    gi0 = min(max(gi0, 0), NWc-1);
    gj0 = min(max(gj0, 0), NHc-1);

    int idx = b*NTc + t;

    float gpx[Kc], gpy[Kc];
#pragma unroll
    for (int k = 0; k < Kc; ++k) {
        gpx[k] = gxr[k]*640.0f;
        gpy[k] = gyr[k]*480.0f;
        d_txv[idx*Kc+k] = gxr[k]*(float)NWc - (float)gi0;
        d_tyv[idx*Kc+k] = gyr[k]*(float)NHc - (float)gj0;
    }
    float* gt = &d_gtn[idx*20];
#pragma unroll
    for (int g = 0; g < 4; ++g) {
        gt[g*4+0] = -gpx[2*g];  gt[g*4+1] = -gpx[2*g+1];
        gt[g*4+2] = -gpy[2*g];  gt[g*4+3] = -gpy[2*g+1];
    }
    gt[16] = -gpx[8]; gt[17] = -gpy[8]; gt[18] = 0.0f; gt[19] = 0.0f;

    // best anchor by IoU on (gw, gh); first max wins (strict >)
    float gw = row[Lc-2]*(float)NWc;
    float gh = row[Lc-1]*(float)NHc;
    float best = -1.0f; int bn = 0;
#pragma unroll
    for (int a = 0; a < NAc; ++a) {
        float aw = c_anch[2*a], ah = c_anch[2*a+1];
        float mw = fminf(aw, gw), mh = fminf(ah, gh);
        float inter = mw*mh;
        float iou = inter / (aw*ah + gw*gh - inter);
        if (iou > best) { best = iou; bn = a; }
    }
    d_codeA[idx] = bn*NPIX + gj0*NWc + gi0;
    d_tclsA[idx] = row[0];

    // conf_t: gather pred box from batch (b-1 mod NB), anchor NA-1, cell (gj0, gi0)
    int bp = (b + NBc - 1) % NBc;
    const float* cb = out + ((size_t)(bp*NAc + (NAc-1))*CH)*NPIX
                          + (size_t)(gj0*NWc + gi0);
    float acc = 0.0f;
#pragma unroll
    for (int k = 0; k < Kc; ++k) {
        float xv = cb[(2*k)*NPIX];
        float yv = cb[(2*k+1)*NPIX];
        if (k == 0) { xv = sigmoidf_(xv); yv = sigmoidf_(yv); }
        float px = (xv + (float)gi0) * (1.0f/(float)NWc);
        float py = (yv + (float)gj0) * (1.0f/(float)NHc);
        float dx = (px - gxr[k]) * 640.0f;
        float dy = (py - gyr[k]) * 480.0f;
        float d2 = fmaf(dx, dx, dy*dy);
        if (d2 < TH2f) {
            float d = sqrtf(d2);
            acc += (expf(2.0f - d*0.025f) - 1.0f) * INVC0;
        }
    }
    d_conft[idx] = acc * (1.0f/(float)Kc);
}

// COLD: full exact rescan of all targets for one cell. Decision logic
// identical to the screen/reference: count corners with d^2 < TH^2; if >= 6,
// exact corner-conf sum; max over targets.
__device__ __noinline__ float rescan_cell(const float* __restrict__ cb,
                                          const float* __restrict__ sgt,
                                          int cell, int nv)
{
    int a = cell / NPIX, pos = cell - a*NPIX;
    int jj = pos / NWc, ii = pos - jj*NWc;
    float fx = (float)ii * SXc, fy = (float)jj * SYc;
    float pxs[Kc], pys[Kc];
#pragma unroll
    for (int k = 0; k < Kc; ++k) {
        float xv = cb[(2*k)*NPIX];
        float yv = cb[(2*k+1)*NPIX];
        if (k == 0) { xv = sigmoidf_(xv); yv = sigmoidf_(yv); }
        pxs[k] = fmaf(xv, SXc, fx);
        pys[k] = fmaf(yv, SYc, fy);
    }
    float m = 0.0f;
    for (int t = 0; t < nv; ++t) {
        const float* tp = &sgt[t*20];
        int cnt = 0;
        float d2s[Kc];
#pragma unroll
        for (int k = 0; k < Kc; ++k) {
            float ngx = (k < 8) ? tp[(k>>1)*4 + (k&1)]     : tp[16];
            float ngy = (k < 8) ? tp[(k>>1)*4 + 2 + (k&1)] : tp[17];
            float dx = pxs[k] + ngx;
            float dy = pys[k] + ngy;
            float dd = fmaf(dx, dx, fmaf(dy, dy, -TH2f));
            d2s[k] = dd;
            cnt += (__float_as_uint(dd) >> 31);
        }
        if (cnt >= 6) {
            float acc = 0.0f;
#pragma unroll
            for (int k = 0; k < Kc; ++k) {
                if (d2s[k] < 0.0f) {
                    float d = sqrtf(d2s[k] + TH2f);
                    acc += (expf(2.0f - d*0.025f) - 1.0f) * INVC0;
                }
            }
            m = fmaxf(m, acc);
        }
    }
    return m;
}

// rare per-object-cell / noobj epilogue
__device__ __noinline__ float cell_loss(const float* __restrict__ cb,
                                        int b, int win, int doconf, int over_sil,
                                        const float* __restrict__ sconft,
                                        const float* __restrict__ stcls)
{
    float contrib = 0.0f;
    if (win >= 0) {
        const float* txp = &d_txv[(b*NTc + win)*Kc];
        const float* typ = &d_tyv[(b*NTc + win)*Kc];
        float cl = 0.0f;
#pragma unroll
        for (int k = 0; k < Kc; ++k) {
            float xv = cb[(2*k)*NPIX];
            float yv = cb[(2*k+1)*NPIX];
            if (k == 0) { xv = sigmoidf_(xv); yv = sigmoidf_(yv); }
            float exd = xv - txp[k];
            float eyd = yv - typ[k];
            cl += exd*exd + eyd*eyd;
        }
        contrib = 0.5f*cl;

        float lg[NCc];
        float mx = -1e30f;
#pragma unroll
        for (int c = 0; c < NCc; ++c) {
            lg[c] = cb[(2*Kc+1+c)*NPIX];
            mx = fmaxf(mx, lg[c]);
        }
        float se = 0.0f;
#pragma unroll
        for (int c = 0; c < NCc; ++c) se += expf(lg[c]-mx);
        int lab = (int)stcls[win];
        lab = min(max(lab, 0), NCc-1);
        contrib += (mx + logf(se)) - lg[lab];

        if (doconf) {
            float conf = sigmoidf_(cb[(2*Kc)*NPIX]);
            float dc = conf - sconft[win];
            contrib += 0.5f*OBJf*dc*dc;
        }
    } else {
        if (doconf && !over_sil) {
            float conf = sigmoidf_(cb[(2*Kc)*NPIX]);
            contrib += 0.5f*conf*conf;
        }
    }
    return contrib;
}

// grid: (14, NB) ; one thread per cell (256 cells per block)
__global__ __launch_bounds__(256, 4)
void region_main(const float* __restrict__ out,
                 const int*   __restrict__ ep,
                 float* __restrict__ loss)
{
    int b   = blockIdx.y;
    int tid = threadIdx.x;
    int cell = blockIdx.x*256 + tid;

    __shared__ __align__(16) float sgt[NTc*20];
    __shared__ float sconft[NTc], stcls[NTc];
    __shared__ int   scode[NTc];
    __shared__ uint  sbm[NBMW];
    __shared__ float wred[8];
    __shared__ int   snv;

    {
        const float4* src = (const float4*)&d_gtn[b*NTc*20];
        float4* dst = (float4*)sgt;
        for (int i2 = tid; i2 < NTc*20/4; i2 += 256) dst[i2] = src[i2];
    }
    if (tid < NBMW) sbm[tid] = 0u;
    if (tid == 0) snv = d_nvalid[b];
    if (tid < NTc) {
        sconft[tid] = d_conft[b*NTc + tid];
        stcls[tid]  = d_tclsA[b*NTc + tid];
        scode[tid]  = d_codeA[b*NTc + tid];
    }
    __syncthreads();      // bitmap fully zeroed + scode/snv visible
    if (tid < NTc && tid < snv) {
        int code = scode[tid];
        atomicOr(&sbm[code >> 5], 1u << (code & 31));
    }
    __syncthreads();

    int act = (cell < NANCH);

    // per-cell packed state: 4 pair groups + scalar corner 8
    ull px[4], py[4];
    float px8 = 60000.0f, py8 = 60000.0f;
    const float* cb = out;
    {
        ull big = pack2(1e30f, 1e30f);
#pragma unroll
        for (int g = 0; g < 4; ++g) { px[g] = big; py[g] = big; }
    }
    if (act) {
        int a = cell / NPIX, pos = cell - a*NPIX;
        int jj = pos / NWc, ii = pos - jj*NWc;
        cb = out + ((size_t)(b*NAc + a)*CH)*NPIX + (size_t)pos;
        float fx = (float)ii * SXc, fy = (float)jj * SYc;
        float pxs[Kc], pys[Kc];
#pragma unroll
        for (int k = 0; k < Kc; ++k) {
            float xv = cb[(2*k)*NPIX];
            float yv = cb[(2*k+1)*NPIX];
            if (k == 0) { xv = sigmoidf_(xv); yv = sigmoidf_(yv); }
            pxs[k] = fmaf(xv, SXc, fx);
            pys[k] = fmaf(yv, SYc, fy);
        }
#pragma unroll
        for (int g = 0; g < 4; ++g) {
            px[g] = pack2(pxs[2*g], pxs[2*g+1]);
            py[g] = pack2(pys[2*g], pys[2*g+1]);
        }
        px8 = pxs[8]; py8 = pys[8];
    }

    const ull nTH2 = pack2(-TH2f, -TH2f);
    int nv = snv;
    int macc = 0;

    // Staged branchless-ish hot loop (1 cell, unroll 2):
    // Stage 1 tests corners 0..5 only. Pigeonhole: cnt_total >= 6 over 9
    // corners implies cnt >= 3 among corners 0..5 — so targets with
    // acc6 > -3 provably cannot trigger the screen (skip stage 2).
    // Stage 2 (warp-rare, ~14%) completes the exact 9-corner count.
#pragma unroll 2
    for (int t = 0; t < nv; ++t) {
        const float* tp = &sgt[t*20];
        const ulonglong2* q = (const ulonglong2*)tp;
        ulonglong2 q0 = q[0], q1 = q[1], q2 = q[2];

        ull d0 = dist2m(px[0], py[0], q0.x, q0.y, nTH2);
        ull d1 = dist2m(px[1], py[1], q1.x, q1.y, nTH2);
        ull d2 = dist2m(px[2], py[2], q2.x, q2.y, nTH2);

        int acc6 = dp4a_sel(prmt_sgn(d0), 0x0101u,
                   dp4a_sel(prmt_sgn(d1), 0x0101u,
                   dp4a_sel(prmt_sgn(d2), 0x0101u, 0)));

        if (acc6 <= -3) {
            ulonglong2 q3 = q[3];
            ull q4 = *(const ull*)(tp + 16);      // (-gx8, -gy8)
            ull d3 = dist2m(px[3], py[3], q3.x, q3.y, nTH2);
            float ngx8 = __uint_as_float((uint)q4);
            float ngy8 = __uint_as_float((uint)(q4 >> 32));
            float dx8 = px8 + ngx8;
            float dy8 = py8 + ngy8;
            float d8  = fmaf(dx8, dx8, fmaf(dy8, dy8, -TH2f));

            int acc = dp4a_sel(prmt_sgn(d3), 0x0101u, acc6);
            acc -= (int)(__float_as_uint(d8) >> 31);
            macc = min(macc, acc);
        }
    }

    // acc = -(#corners inside). mean-conf > 0.6 (sum > 5.4) requires >= 6
    // corners within TH (each corner conf <= 1). Cold rescan only if any
    // target could pass (per-lane rare).
    float m = 0.0f;
    if (macc <= -6) m = rescan_cell(cb, sgt, cell, nv);

    int doconf = (ep[0] > 15) ? 1 : 0;
    float contrib = 0.0f;
    if (act) {
        int over = (m * (1.0f/(float)Kc)) > SILf;
        int win = -1;
        if (sbm[cell >> 5] & (1u << (cell & 31))) {
            for (int t = nv-1; t >= 0; --t)
                if (scode[t] == cell) { win = t; break; }
        }
        if (win >= 0 || (doconf && !over))
            contrib = cell_loss(cb, b, win, doconf, over, sconft, stcls);
    }

    // warp-shuffle reduction + one atomic per block
#pragma unroll
    for (int off = 16; off > 0; off >>= 1)
        contrib += __shfl_down_sync(0xFFFFFFFFu, contrib, off);
    int lane = tid & 31, wid = tid >> 5;
    if (lane == 0) wred[wid] = contrib;
    __syncthreads();
    if (tid < 8) {
        float v = wred[tid];
#pragma unroll
        for (int off = 4; off > 0; off >>= 1)
            v += __shfl_down_sync(0xFFu, v, off);
        if (tid == 0) atomicAdd(loss, v);
    }
}

extern "C" void kernel_launch(void* const* d_in, const int* in_sizes, int n_in,
                              void* d_out, int out_size)
{
    const float* out = (const float*)d_in[0];
    const float* tgt = (const float*)d_in[1];
    const int*   ep  = (const int*)d_in[2];
    float* loss = (float*)d_out;

    region_prep<<<NBc, 64>>>(out, tgt, loss);
    dim3 g((NANCH + 255)/256, NBc);
    region_main<<<g, 256>>>(out, ep, loss);
}